// round 1
// baseline (speedup 1.0000x reference)
#include <cuda_runtime.h>

// Global scratch accumulator (allocation-free per harness rules).
__device__ float g_acc;

__global__ void hcl_zero_kernel() {
    g_acc = 0.0f;
}

__global__ void __launch_bounds__(256)
hcl_main_kernel(const float* __restrict__ pred,
                const int* __restrict__ i_idx,
                const int* __restrict__ j_idx,
                long long rows, int num_classes)
{
    // Indices are tiny, identical for all threads: broadcast-cached loads.
    const int i0 = __ldg(i_idx + 0), i1 = __ldg(i_idx + 1),
              i2 = __ldg(i_idx + 2), i3 = __ldg(i_idx + 3);
    const int j0 = __ldg(j_idx + 0), j1 = __ldg(j_idx + 1),
              j2 = __ldg(j_idx + 2), j3 = __ldg(j_idx + 3);

    float acc = 0.0f;

    long long tid    = (long long)blockIdx.x * blockDim.x + threadIdx.x;
    long long stride = (long long)gridDim.x * blockDim.x;

    for (long long r = tid; r < rows; r += stride) {
        const float* row = pred + r * num_classes;
        // 8 independent loads -> good MLP; warp-adjacent rows keep sectors
        // resident in L1 across the 8 column accesses.
        float a0 = __ldg(row + i0), b0 = __ldg(row + j0);
        float a1 = __ldg(row + i1), b1 = __ldg(row + j1);
        float a2 = __ldg(row + i2), b2 = __ldg(row + j2);
        float a3 = __ldg(row + i3), b3 = __ldg(row + j3);
        float d0 = fmaxf(a0 - b0, 0.0f);
        float d1 = fmaxf(a1 - b1, 0.0f);
        float d2 = fmaxf(a2 - b2, 0.0f);
        float d3 = fmaxf(a3 - b3, 0.0f);
        acc = fmaf(d0, d0, acc);
        acc = fmaf(d1, d1, acc);
        acc = fmaf(d2, d2, acc);
        acc = fmaf(d3, d3, acc);
    }

    // Warp reduction
    #pragma unroll
    for (int off = 16; off > 0; off >>= 1)
        acc += __shfl_xor_sync(0xFFFFFFFFu, acc, off);

    // Block reduction via shared, single global atomic per block
    __shared__ float s_part;
    if (threadIdx.x == 0) s_part = 0.0f;
    __syncthreads();
    if ((threadIdx.x & 31) == 0) atomicAdd(&s_part, acc);
    __syncthreads();
    if (threadIdx.x == 0) atomicAdd(&g_acc, s_part);
}

__global__ void hcl_finalize_kernel(const float* __restrict__ temperature,
                                    float* __restrict__ out,
                                    long long rows, int num_constraints)
{
    out[0] = g_acc / ((float)rows * temperature[0] * (float)num_constraints);
}

extern "C" void kernel_launch(void* const* d_in, const int* in_sizes, int n_in,
                              void* d_out, int out_size)
{
    const float* pred  = (const float*)d_in[0];
    const float* temp  = (const float*)d_in[1];
    const int*   i_idx = (const int*)d_in[2];
    const int*   j_idx = (const int*)d_in[3];
    float* out = (float*)d_out;

    const int num_classes = 14;                       // fixed problem shape
    const long long rows = (long long)in_sizes[0] / num_classes;
    const int num_constraints = in_sizes[2];          // 4

    hcl_zero_kernel<<<1, 1>>>();

    const int threads = 256;
    long long want = (rows + threads - 1) / threads;
    int blocks = (int)(want < 2368 ? want : 2368);    // 148 SMs * 16
    hcl_main_kernel<<<blocks, threads>>>(pred, i_idx, j_idx, rows, num_classes);

    hcl_finalize_kernel<<<1, 1>>>(temp, out, rows, num_constraints);
}